// round 1
// baseline (speedup 1.0000x reference)
#include <cuda_runtime.h>
#include <math.h>

// Problem constants
#define NTOT   131072
#define DIM    512
#define DATT   256
#define NHEAD  4
#define NCLS   53
#define BAGSZ  16
#define NBAGS  8192

// Kernel-1 tiling
#define TM 64          // rows (sentences) per block = 4 bags
#define TK 32          // K chunk streamed through smem

// Kernel-2 tiling
#define TB  32         // bags per block
#define TKC 64         // K chunk
#define NCP 56         // classes padded to 8*7

// Scratch for bag representations (16 MB) — __device__ global per allocation rules.
__device__ float g_bag[(size_t)NBAGS * DIM];

// Dynamic smem layout (floats):
//   xs  : TM*DIM        (64*512   = 32768)
//   ws  : TK*DATT       (32*256   =  8192)
//   w2s : DATT*NHEAD    (256*4    =  1024)
//   ss  : TM*NHEAD      (64*4     =   256)
//   wr  : TM            (64)
#define SMEM_FLOATS (TM*DIM + TK*DATT + DATT*NHEAD + TM*NHEAD + TM)
#define SMEM_BYTES  (SMEM_FLOATS * 4)

extern __shared__ float smem[];

__global__ __launch_bounds__(256)
void score_pool_kernel(const float* __restrict__ x,
                       const float* __restrict__ W1,
                       const float* __restrict__ W2)
{
    float* xs  = smem;                  // [TM][DIM]
    float* ws  = xs  + TM * DIM;        // [TK][DATT]
    float* w2s = ws  + TK * DATT;       // [DATT][NHEAD]
    float* ss  = w2s + DATT * NHEAD;    // [TM][NHEAD]
    float* wr  = ss  + TM * NHEAD;      // [TM]

    const int tid    = threadIdx.x;
    const int row0_g = blockIdx.x * TM;

    // ---- load x tile (64x512) with float4 ----
    {
        const float4* xg  = (const float4*)(x + (size_t)row0_g * DIM);
        float4*       xs4 = (float4*)xs;
        #pragma unroll
        for (int i = tid; i < TM * DIM / 4; i += 256) xs4[i] = xg[i];
    }
    // ---- load W2 (256x4) ----
    for (int i = tid; i < DATT * NHEAD; i += 256) w2s[i] = W2[i];
    // ---- zero per-row score accumulators (exactly 256 entries) ----
    ss[tid] = 0.0f;
    __syncthreads();

    // micro-tile: thread -> 8 rows x 8 cols
    const int tx = tid & 31;      // col group
    const int ty = tid >> 5;      // row group
    const int r0 = ty * 8;
    const int c0 = tx * 4;        // cols [c0..c0+3] and [128+c0..128+c0+3]

    float acc[8][8];
    #pragma unroll
    for (int i = 0; i < 8; i++)
        #pragma unroll
        for (int j = 0; j < 8; j++) acc[i][j] = 0.0f;

    // ---- main GEMM: h = x @ W1, K streamed in TK chunks ----
    for (int k0 = 0; k0 < DIM; k0 += TK) {
        __syncthreads();   // previous chunk consumed before overwrite
        {
            const float4* wg  = (const float4*)(W1 + (size_t)k0 * DATT);
            float4*       ws4 = (float4*)ws;
            #pragma unroll
            for (int i = tid; i < TK * DATT / 4; i += 256) ws4[i] = wg[i];
        }
        __syncthreads();

        #pragma unroll 2
        for (int kk4 = 0; kk4 < TK / 4; kk4++) {
            float4 a4[8];
            #pragma unroll
            for (int i = 0; i < 8; i++)
                a4[i] = *(const float4*)&xs[(r0 + i) * DIM + k0 + kk4 * 4];

            #pragma unroll
            for (int s = 0; s < 4; s++) {
                const float4 b0 = *(const float4*)&ws[(kk4 * 4 + s) * DATT + c0];
                const float4 b1 = *(const float4*)&ws[(kk4 * 4 + s) * DATT + 128 + c0];
                #pragma unroll
                for (int i = 0; i < 8; i++) {
                    const float a = (s == 0) ? a4[i].x : (s == 1) ? a4[i].y
                                  : (s == 2) ? a4[i].z : a4[i].w;
                    acc[i][0] += a * b0.x;
                    acc[i][1] += a * b0.y;
                    acc[i][2] += a * b0.z;
                    acc[i][3] += a * b0.w;
                    acc[i][4] += a * b1.x;
                    acc[i][5] += a * b1.y;
                    acc[i][6] += a * b1.z;
                    acc[i][7] += a * b1.w;
                }
            }
        }
    }

    // ---- epilogue: tanh, project to per-head scores, reduce into ss ----
    #pragma unroll
    for (int i = 0; i < 8; i++) {
        float sp[NHEAD] = {0.f, 0.f, 0.f, 0.f};
        #pragma unroll
        for (int j = 0; j < 8; j++) {
            const int col = (j < 4) ? (c0 + j) : (128 + c0 + (j - 4));
            const float t = tanhf(acc[i][j]);
            #pragma unroll
            for (int h = 0; h < NHEAD; h++) sp[h] += t * w2s[col * NHEAD + h];
        }
        #pragma unroll
        for (int h = 0; h < NHEAD; h++)
            atomicAdd(&ss[(r0 + i) * NHEAD + h], sp[h]);
    }
    __syncthreads();

    // ---- per-bag softmax (16 rows), mean over heads -> per-row weight ----
    if (tid < TM) {
        const int r  = tid;
        const int b0 = (r >> 4) << 4;          // bag start row within tile
        float wsum = 0.0f;
        #pragma unroll
        for (int h = 0; h < NHEAD; h++) {
            float m = -1e30f;
            #pragma unroll
            for (int q = 0; q < BAGSZ; q++)
                m = fmaxf(m, ss[(b0 + q) * NHEAD + h]);
            float den = 0.0f;
            #pragma unroll
            for (int q = 0; q < BAGSZ; q++)
                den += expf(ss[(b0 + q) * NHEAD + h] - m);
            wsum += expf(ss[r * NHEAD + h] - m) / den;
        }
        wr[r] = wsum * (1.0f / NHEAD);
    }
    __syncthreads();

    // ---- weighted bag sums: 4 bags x 512 dims; thread owns 2 dims ----
    const int d0 = tid * 2;
    #pragma unroll
    for (int b = 0; b < TM / BAGSZ; b++) {
        float s0 = 0.0f, s1 = 0.0f;
        #pragma unroll
        for (int q = 0; q < BAGSZ; q++) {
            const float w = wr[b * BAGSZ + q];
            s0 += w * xs[(b * BAGSZ + q) * DIM + d0];
            s1 += w * xs[(b * BAGSZ + q) * DIM + d0 + 1];
        }
        const int bg = blockIdx.x * (TM / BAGSZ) + b;
        g_bag[(size_t)bg * DIM + d0]     = s0;
        g_bag[(size_t)bg * DIM + d0 + 1] = s1;
    }
}

__global__ __launch_bounds__(256)
void classifier_kernel(const float* __restrict__ Wc,
                       const float* __restrict__ bc,
                       float* __restrict__ out)
{
    __shared__ float bs[TB][TKC + 1];   // pad -> conflict-free row access
    __shared__ float wcs[TKC][NCP];

    const int tid  = threadIdx.x;
    const int bag0 = blockIdx.x * TB;
    const int r    = tid & 31;          // bag within tile
    const int cy   = tid >> 5;          // class group: cols cy*7 .. cy*7+6

    float acc[7] = {0.f, 0.f, 0.f, 0.f, 0.f, 0.f, 0.f};

    for (int k0 = 0; k0 < DIM; k0 += TKC) {
        __syncthreads();
        // load bag_repr chunk 32x64 (each thread: 8 consecutive floats)
        {
            const int rr = tid >> 3;
            const int cc = (tid & 7) * 8;
            const float* src = g_bag + (size_t)(bag0 + rr) * DIM + k0 + cc;
            const float4 v0 = *(const float4*)src;
            const float4 v1 = *(const float4*)(src + 4);
            bs[rr][cc + 0] = v0.x; bs[rr][cc + 1] = v0.y;
            bs[rr][cc + 2] = v0.z; bs[rr][cc + 3] = v0.w;
            bs[rr][cc + 4] = v1.x; bs[rr][cc + 5] = v1.y;
            bs[rr][cc + 6] = v1.z; bs[rr][cc + 7] = v1.w;
        }
        // load Wc chunk 64x53 (padded to 56)
        for (int idx = tid; idx < TKC * NCP; idx += 256) {
            const int kk = idx / NCP;
            const int c  = idx % NCP;
            wcs[kk][c] = (c < NCLS) ? Wc[(size_t)(k0 + kk) * NCLS + c] : 0.0f;
        }
        __syncthreads();

        #pragma unroll 8
        for (int kk = 0; kk < TKC; kk++) {
            const float a = bs[r][kk];
            #pragma unroll
            for (int j = 0; j < 7; j++)
                acc[j] += a * wcs[kk][cy * 7 + j];
        }
    }

    #pragma unroll
    for (int j = 0; j < 7; j++) {
        const int c = cy * 7 + j;
        if (c < NCLS)
            out[(size_t)(bag0 + r) * NCLS + c] = acc[j] + bc[c];
    }
}

extern "C" void kernel_launch(void* const* d_in, const int* in_sizes, int n_in,
                              void* d_out, int out_size)
{
    const float* x  = (const float*)d_in[0];
    const float* W1 = (const float*)d_in[1];
    const float* W2 = (const float*)d_in[2];
    const float* Wc = (const float*)d_in[3];
    const float* bc = (const float*)d_in[4];
    float* out = (float*)d_out;

    // opt-in to >48KB dynamic smem (immediate API, not captured in graph)
    cudaFuncSetAttribute(score_pool_kernel,
                         cudaFuncAttributeMaxDynamicSharedMemorySize, SMEM_BYTES);

    score_pool_kernel<<<NTOT / TM, 256, SMEM_BYTES>>>(x, W1, W2);
    classifier_kernel<<<NBAGS / TB, 256>>>(Wc, bc, out);
}

// round 2
// speedup vs baseline: 2.3766x; 2.3766x over previous
#include <cuda_runtime.h>
#include <cuda_bf16.h>
#include <mma.h>
#include <math.h>

using namespace nvcuda;

// Problem constants
#define NTOT   131072
#define DIM    512
#define DATT   256
#define NHEAD  4
#define NCLS   53
#define BAGSZ  16
#define NBAGS  8192

// Kernel-1 tiling
#define TM   64         // rows per block (4 bags)
#define KC   64         // K chunk for B staging
#define A_LD 520        // bf16 elems per A row (512 + 8 pad -> conflict-free ldsm)
#define B_LD 264        // bf16 elems per B row (256 + 8 pad)
#define H_LD 260        // f32 elems per h row (256 + 4 pad, mult of 4 for wmma store)

// smem byte offsets
#define OFF_A_HI  0
#define OFF_A_LO  (TM * A_LD * 2)                       // 66560
#define OFF_B     (OFF_A_LO + TM * A_LD * 2)            // 133120
#define OFF_B_LO  (OFF_B + KC * B_LD * 2)               // +33792
#define OFF_H     OFF_B                                  // h overlaps B (used after GEMM)
#define OFF_W2    (OFF_B + 2 * KC * B_LD * 2)           // 200704
#define OFF_SS    (OFF_W2 + DATT * NHEAD * 4)           // 204800
#define OFF_WR    (OFF_SS + TM * NHEAD * 4)             // 205824
#define SMEM_BYTES (OFF_WR + TM * 4)                    // 206080

__device__ float g_bag[(size_t)NBAGS * DIM];

extern __shared__ char smem_raw[];

__device__ __forceinline__ void split_store4(float4 v, __nv_bfloat16* hi, __nv_bfloat16* lo)
{
    __nv_bfloat16 h0 = __float2bfloat16(v.x);
    __nv_bfloat16 h1 = __float2bfloat16(v.y);
    __nv_bfloat16 h2 = __float2bfloat16(v.z);
    __nv_bfloat16 h3 = __float2bfloat16(v.w);
    hi[0] = h0; hi[1] = h1; hi[2] = h2; hi[3] = h3;
    lo[0] = __float2bfloat16(v.x - __bfloat162float(h0));
    lo[1] = __float2bfloat16(v.y - __bfloat162float(h1));
    lo[2] = __float2bfloat16(v.z - __bfloat162float(h2));
    lo[3] = __float2bfloat16(v.w - __bfloat162float(h3));
}

__global__ __launch_bounds__(256)
void score_pool_kernel(const float* __restrict__ x,
                       const float* __restrict__ W1,
                       const float* __restrict__ W2)
{
    __nv_bfloat16* A_hi = (__nv_bfloat16*)(smem_raw + OFF_A_HI);
    __nv_bfloat16* A_lo = (__nv_bfloat16*)(smem_raw + OFF_A_LO);
    __nv_bfloat16* B_hi = (__nv_bfloat16*)(smem_raw + OFF_B);
    __nv_bfloat16* B_lo = (__nv_bfloat16*)(smem_raw + OFF_B_LO);
    float* hbuf = (float*)(smem_raw + OFF_H);
    float* w2s  = (float*)(smem_raw + OFF_W2);
    float* ss   = (float*)(smem_raw + OFF_SS);
    float* wr   = (float*)(smem_raw + OFF_WR);

    const int tid  = threadIdx.x;
    const int row0 = blockIdx.x * TM;

    // ---- load x tile 64x512 fp32, split into bf16 hi/lo in smem ----
    {
        const float4* xg = (const float4*)(x + (size_t)row0 * DIM);
        #pragma unroll 4
        for (int i = tid; i < (TM * DIM) / 4; i += 256) {
            float4 v = xg[i];
            const int r = i >> 7;            // DIM/4 = 128
            const int c = (i & 127) * 4;
            split_store4(v, &A_hi[r * A_LD + c], &A_lo[r * A_LD + c]);
        }
    }
    // W2 (256x4) and score accumulator init
    for (int i = tid; i < DATT * NHEAD; i += 256) w2s[i] = W2[i];
    ss[tid] = 0.0f;   // exactly TM*NHEAD = 256 entries

    // ---- warp tiling: 8 warps = 2 (M) x 4 (N); warp tile 32x64 ----
    const int wid    = tid >> 5;
    const int warp_m = wid >> 2;   // 0..1
    const int warp_n = wid & 3;    // 0..3

    wmma::fragment<wmma::accumulator, 16, 16, 16, float> acc[2][4];
    #pragma unroll
    for (int i = 0; i < 2; i++)
        #pragma unroll
        for (int j = 0; j < 4; j++)
            wmma::fill_fragment(acc[i][j], 0.0f);

    // ---- main GEMM: h = x @ W1 as 3-term bf16 split ----
    for (int k0 = 0; k0 < DIM; k0 += KC) {
        __syncthreads();   // prior chunk consumed
        // stage+split B chunk: W1[k0:k0+64, 0:256]
        #pragma unroll 4
        for (int i = tid; i < (KC * DATT) / 4; i += 256) {
            const int r = i >> 6;            // DATT/4 = 64
            const int c = (i & 63) * 4;
            float4 v = *(const float4*)(W1 + (size_t)(k0 + r) * DATT + c);
            split_store4(v, &B_hi[r * B_LD + c], &B_lo[r * B_LD + c]);
        }
        __syncthreads();

        #pragma unroll
        for (int pass = 0; pass < 3; pass++) {
            const __nv_bfloat16* As = (pass == 2) ? A_lo : A_hi;
            const __nv_bfloat16* Bs = (pass == 1) ? B_lo : B_hi;
            #pragma unroll
            for (int kk = 0; kk < KC; kk += 16) {
                wmma::fragment<wmma::matrix_a, 16, 16, 16, __nv_bfloat16, wmma::row_major> af[2];
                wmma::fragment<wmma::matrix_b, 16, 16, 16, __nv_bfloat16, wmma::row_major> bf[4];
                #pragma unroll
                for (int i = 0; i < 2; i++)
                    wmma::load_matrix_sync(af[i],
                        As + (size_t)(warp_m * 32 + i * 16) * A_LD + (k0 + kk), A_LD);
                #pragma unroll
                for (int j = 0; j < 4; j++)
                    wmma::load_matrix_sync(bf[j],
                        Bs + (size_t)kk * B_LD + warp_n * 64 + j * 16, B_LD);
                #pragma unroll
                for (int i = 0; i < 2; i++)
                    #pragma unroll
                    for (int j = 0; j < 4; j++)
                        wmma::mma_sync(acc[i][j], af[i], bf[j], acc[i][j]);
            }
        }
    }

    __syncthreads();   // B region dead -> reuse as hbuf
    #pragma unroll
    for (int i = 0; i < 2; i++)
        #pragma unroll
        for (int j = 0; j < 4; j++)
            wmma::store_matrix_sync(
                hbuf + (size_t)(warp_m * 32 + i * 16) * H_LD + warp_n * 64 + j * 16,
                acc[i][j], H_LD, wmma::mem_row_major);
    __syncthreads();

    // ---- scores: s[r][h] = sum_c tanh(h[r][c]) * W2[c][h] ----
    {
        const int r = tid & 63;
        const int q = tid >> 6;           // column quarter, 0..3
        float sp0 = 0.f, sp1 = 0.f, sp2 = 0.f, sp3 = 0.f;
        const float* hr = hbuf + (size_t)r * H_LD + q * 64;
        #pragma unroll
        for (int jj = 0; jj < 16; jj++) {
            const float4 hv = *(const float4*)&hr[jj * 4];
            #pragma unroll
            for (int s = 0; s < 4; s++) {
                const float hvv = (s == 0) ? hv.x : (s == 1) ? hv.y : (s == 2) ? hv.z : hv.w;
                const float t = tanhf(hvv);
                const int c = q * 64 + jj * 4 + s;
                const float4 w2v = *(const float4*)&w2s[c * 4];
                sp0 += t * w2v.x; sp1 += t * w2v.y;
                sp2 += t * w2v.z; sp3 += t * w2v.w;
            }
        }
        atomicAdd(&ss[r * 4 + 0], sp0);
        atomicAdd(&ss[r * 4 + 1], sp1);
        atomicAdd(&ss[r * 4 + 2], sp2);
        atomicAdd(&ss[r * 4 + 3], sp3);
    }
    __syncthreads();

    // ---- per-bag softmax over 16 rows, mean over heads ----
    if (tid < TM) {
        const int r  = tid;
        const int b0 = (r >> 4) << 4;
        float wsum = 0.0f;
        #pragma unroll
        for (int h = 0; h < NHEAD; h++) {
            float m = -1e30f;
            #pragma unroll
            for (int q = 0; q < BAGSZ; q++)
                m = fmaxf(m, ss[(b0 + q) * NHEAD + h]);
            float den = 0.0f;
            #pragma unroll
            for (int q = 0; q < BAGSZ; q++)
                den += expf(ss[(b0 + q) * NHEAD + h] - m);
            wsum += expf(ss[r * NHEAD + h] - m) / den;
        }
        wr[r] = wsum * (1.0f / NHEAD);
    }
    __syncthreads();

    // ---- weighted bag sums from reconstructed x (hi+lo) ----
    const int d0 = tid * 2;
    #pragma unroll
    for (int b = 0; b < TM / BAGSZ; b++) {
        float s0 = 0.0f, s1 = 0.0f;
        #pragma unroll
        for (int q = 0; q < BAGSZ; q++) {
            const int rr = b * BAGSZ + q;
            const float w = wr[rr];
            const float v0 = __bfloat162float(A_hi[rr * A_LD + d0]) +
                             __bfloat162float(A_lo[rr * A_LD + d0]);
            const float v1 = __bfloat162float(A_hi[rr * A_LD + d0 + 1]) +
                             __bfloat162float(A_lo[rr * A_LD + d0 + 1]);
            s0 += w * v0;
            s1 += w * v1;
        }
        const int bg = blockIdx.x * (TM / BAGSZ) + b;
        *(float2*)&g_bag[(size_t)bg * DIM + d0] = make_float2(s0, s1);
    }
}

// ---------------- classifier: logits = bag_repr @ Wc + bc ----------------
#define TB2 8   // bags per block -> 1024 blocks

__global__ __launch_bounds__(256)
void classifier_kernel(const float* __restrict__ Wc,
                       const float* __restrict__ bc,
                       float* __restrict__ out)
{
    __shared__ float bs[TB2][64];     // bag_repr chunk
    __shared__ float wcs[64][64];     // Wc chunk, classes padded to 64 w/ zeros

    const int tid  = threadIdx.x;
    const int bag0 = blockIdx.x * TB2;
    const int w    = tid >> 5;        // warp = bag
    const int lane = tid & 31;        // classes {lane, lane+32}

    float acc0 = 0.0f, acc1 = 0.0f;

    for (int k0 = 0; k0 < DIM; k0 += 64) {
        __syncthreads();
        // bag chunk: 8 bags x 64 -> 2 floats/thread
        {
            const int idx = tid * 2;
            const int b  = idx >> 6;
            const int kk = idx & 63;
            const float2 v = *(const float2*)(g_bag + (size_t)(bag0 + b) * DIM + k0 + kk);
            bs[b][kk]     = v.x;
            bs[b][kk + 1] = v.y;
        }
        // Wc chunk: 64 x 53 padded to 64
        for (int i = tid; i < 64 * 64; i += 256) {
            const int kk = i >> 6;
            const int c  = i & 63;
            wcs[kk][c] = (c < NCLS) ? Wc[(size_t)(k0 + kk) * NCLS + c] : 0.0f;
        }
        __syncthreads();

        #pragma unroll
        for (int kk = 0; kk < 64; kk++) {
            const float a = bs[w][kk];
            acc0 += a * wcs[kk][lane];
            acc1 += a * wcs[kk][lane + 32];
        }
    }

    out[(size_t)(bag0 + w) * NCLS + lane] = acc0 + bc[lane];
    if (lane + 32 < NCLS)
        out[(size_t)(bag0 + w) * NCLS + lane + 32] = acc1 + bc[lane + 32];
}

extern "C" void kernel_launch(void* const* d_in, const int* in_sizes, int n_in,
                              void* d_out, int out_size)
{
    const float* x  = (const float*)d_in[0];
    const float* W1 = (const float*)d_in[1];
    const float* W2 = (const float*)d_in[2];
    const float* Wc = (const float*)d_in[3];
    const float* bc = (const float*)d_in[4];
    float* out = (float*)d_out;

    cudaFuncSetAttribute(score_pool_kernel,
                         cudaFuncAttributeMaxDynamicSharedMemorySize, SMEM_BYTES);

    score_pool_kernel<<<NTOT / TM, 256, SMEM_BYTES>>>(x, W1, W2);
    classifier_kernel<<<NBAGS / TB2, 256>>>(Wc, bc, out);
}